// round 12
// baseline (speedup 1.0000x reference)
#include <cuda_runtime.h>
#include <cuda_bf16.h>
#include <cstdint>

// Only Z0[:,:,-1] = conv(X0, t=10) is nonzero.  Softmax degree-norm is a no-op.
// Single persistent kernel. Weight streaming via cp.async (LDGSTS) pipelines:
// depth-4 x 32KB smem buffers -> MLP decoupled from registers.

#define NBLK 148
#define NTHR 512
#define NT (NBLK * NTHR)        // 75776
#define NWARP (NBLK * 16)       // 2368

// ---------------- device scratch ----------------
__device__ float g_obs2[2 * 8192];     // MLP input rows t=9,10
__device__ float g_s1[2 * 2048];       // accum (no bias), zeroed in P5
__device__ float g_s2[2 * 2048];       // accum, zeroed in P5
__device__ float g_s3[2 * 12288];      // accum; row0=X9, row1=X10 (pre-bias/relu)
__device__ float g_sph[12 * 256];      // accum (no bias), zeroed in P5
__device__ float g_tph[256];           // plain store (pre-bias)
__device__ float g_U[3 * 1024 * 12];   // [c][n][tau], c = feat-9
__device__ float g_Y[1024 * 12];
__device__ float g_G[3 * 1024 * 12];   // normalized (A@X) rows

// ---------------- grid barrier (sense-reversing, replay-safe) --------------
__device__ unsigned g_bar_cnt[8];
__device__ unsigned g_bar_flag[8];

__device__ __forceinline__ void grid_barrier(int i) {
    __syncthreads();
    if (threadIdx.x == 0) {
        volatile unsigned* fl = &g_bar_flag[i];
        unsigned sense = *fl;
        __threadfence();
        unsigned old = atomicAdd(&g_bar_cnt[i], 1);
        if (old == NBLK - 1) {
            g_bar_cnt[i] = 0;
            __threadfence();
            *fl = sense ^ 1u;
        } else {
            while (*fl == sense) { }
        }
        __threadfence();
    }
    __syncthreads();
}

// ---------------- cp.async helpers ----------------
#define CP_ASYNC16(dst_u32, src_ptr) \
    asm volatile("cp.async.cg.shared.global [%0], [%1], 16;" \
                 :: "r"(dst_u32), "l"(src_ptr))
#define CP_COMMIT() asm volatile("cp.async.commit_group;")
#define CP_WAIT3()  asm volatile("cp.async.wait_group 3;")

// ---- streamed gemv: block owns 2048-col strip x [k0,k1) chunk (<=128 rows).
// A-chunk staged (relu'd) in smem; W streamed via depth-4 cp.async pipeline.
// Each thread loads & consumes its own 16B per row -> no intra-pipe syncs.
template<int NFULL, bool RELU>
__device__ __forceinline__ void gemv_stream(const float* __restrict__ A,
                                            const float* __restrict__ bias,
                                            const float* __restrict__ W,
                                            float* __restrict__ S,
                                            int c0, int k0, int k1, int K,
                                            float* sm) {
    const int tid = threadIdx.x;
    float* sA0 = sm;            // 128 floats
    float* sA1 = sm + 128;      // 128 floats
    float* bufs = sm + 256;     // 4 slots x 4 rows x 2048 floats = 128KB
    const int cnt = k1 - k0;    // 13..86 everywhere (nbuf >= 4)

    for (int i = tid; i < cnt; i += NTHR) {
        float x0 = A[k0 + i], x1 = A[K + k0 + i];
        if (RELU) {
            float bb = bias[k0 + i];
            x0 = fmaxf(x0 + bb, 0.0f); x1 = fmaxf(x1 + bb, 0.0f);
        }
        sA0[i] = x0; sA1[i] = x1;
    }
    __syncthreads();

    const uint32_t bufb = (uint32_t)__cvta_generic_to_shared(bufs);
    const float* Wt = W + c0 + tid * 4;
    const int nbuf = (cnt + 3) >> 2;

    // prologue: 3 buffers in flight
    for (int f = 0; f < 3; ++f) {
        int r0 = f * 4;
        int rn = (cnt - r0 < 4) ? (cnt - r0) : 4;
        for (int r = 0; r < rn; ++r)
            CP_ASYNC16(bufb + (((f & 3) * 8192 + r * 2048 + tid * 4) << 2),
                       Wt + (size_t)(k0 + r0 + r) * NFULL);
        CP_COMMIT();
    }

    float a00 = 0, a01 = 0, a02 = 0, a03 = 0;
    float a10 = 0, a11 = 0, a12 = 0, a13 = 0;
    for (int f = 0; f < nbuf; ++f) {
        int bi = f + 3;
        if (bi < nbuf) {
            int r0 = bi * 4;
            int rn = (cnt - r0 < 4) ? (cnt - r0) : 4;
            for (int r = 0; r < rn; ++r)
                CP_ASYNC16(bufb + (((bi & 3) * 8192 + r * 2048 + tid * 4) << 2),
                           Wt + (size_t)(k0 + r0 + r) * NFULL);
        }
        CP_COMMIT();                 // possibly-empty group keeps accounting exact
        CP_WAIT3();                  // buffer f guaranteed complete
        int r0 = f * 4;
        int rn = (cnt - r0 < 4) ? (cnt - r0) : 4;
        const float* bf = bufs + (f & 3) * 8192 + tid * 4;
        for (int r = 0; r < rn; ++r) {
            float4 w = *reinterpret_cast<const float4*>(bf + r * 2048);
            float x0 = sA0[r0 + r], x1 = sA1[r0 + r];
            a00 += x0 * w.x; a01 += x0 * w.y; a02 += x0 * w.z; a03 += x0 * w.w;
            a10 += x1 * w.x; a11 += x1 * w.y; a12 += x1 * w.z; a13 += x1 * w.w;
        }
    }
    int col = c0 + tid * 4;
    atomicAdd(S + col + 0, a00); atomicAdd(S + col + 1, a01);
    atomicAdd(S + col + 2, a02); atomicAdd(S + col + 3, a03);
    atomicAdd(S + NFULL + col + 0, a10); atomicAdd(S + NFULL + col + 1, a11);
    atomicAdd(S + NFULL + col + 2, a12); atomicAdd(S + NFULL + col + 3, a13);
}

#define SMEM_FLOATS (3 * 12288)     // P4 needs 144KB; gemv needs 129KB

__device__ __forceinline__ float4 relu4b(float4 v, float4 b) {
    v.x = fmaxf(v.x + b.x, 0.0f); v.y = fmaxf(v.y + b.y, 0.0f);
    v.z = fmaxf(v.z + b.z, 0.0f); v.w = fmaxf(v.w + b.w, 0.0f);
    return v;
}

// ---------------- the single mega kernel ----------------
__global__ void __launch_bounds__(NTHR, 1)
mega8_kernel(const float* __restrict__ obs,
             const float* __restrict__ tf,
             const float* __restrict__ fc_w1, const float* __restrict__ b1,
             const float* __restrict__ fc_w2, const float* __restrict__ b2,
             const float* __restrict__ fc_w3, const float* __restrict__ b3,
             const float* __restrict__ Wf, const float* __restrict__ Wb,
             const float* __restrict__ bvec,
             const float* __restrict__ li,
             const float* __restrict__ gs_w1, const float* __restrict__ gs_b1,
             const float* __restrict__ gs_w2, const float* __restrict__ gs_b2,
             const float* __restrict__ gt_w1, const float* __restrict__ gt_b1,
             const float* __restrict__ gt_w2, const float* __restrict__ gt_b2,
             const float* __restrict__ Bm,
             float* __restrict__ out) {
    extern __shared__ float sm[];

    const int tid = threadIdx.x, bid = blockIdx.x;
    const int gt = bid * NTHR + tid;
    const int lane = tid & 31;
    const int gw = gt >> 5;

    // ======== P0: obs gather, out-tail zero, sph split-K (coalesced), tph ==
    for (int i = gt; i < 16384 + 36864; i += NT) {
        if (i < 16384) {
            int m = i >> 13, k = i & 8191;
            int n = k >> 3, d = k & 7;
            g_obs2[i] = obs[n * 96 + d * 12 + 9 + m];
        } else {
            out[12288 + (i - 16384)] = 0.0f;
        }
    }
    if (gt < 24576) {                       // sph: 12 tau x 8 kc x 256 t
        int t = gt & 255;
        int rr = gt >> 8;
        int tau = rr / 8, kc = rr & 7;
        const float* lr = li + tau * 1024 + kc * 128;
        const float* w  = gs_w1 + (size_t)(kc * 128) * 256 + t;
        float acc = 0.0f;
#pragma unroll 16
        for (int k = 0; k < 128; ++k) acc += lr[k] * w[(size_t)k * 256];
        atomicAdd(&g_sph[tau * 256 + t], acc);
    } else if (gt < 24832) {                // tph
        int t = gt - 24576;
        float acc = 0.0f;
#pragma unroll
        for (int k = 0; k < 36; ++k) acc += tf[k] * gt_w1[k * 256 + t];
        g_tph[t] = acc;                     // bias at read
    }
    grid_barrier(0);

    // ======== P1: u (blocks 0..47)  ||  gemv1 streamed (48..147) ===========
    if (bid < 48) {
        int lw = bid * 16 + (tid >> 5);     // 0..767
        for (int task = lw; task < 3072; task += 768) {
            int n = task / 3, c = task - n * 3;
            int j = n * 12 + 9 + c;
            float wg[8], wt[8], bg[8];
#pragma unroll
            for (int i = 0; i < 8; ++i) {
                int k = lane + 32 * i;
                wg[i] = gs_w2[(size_t)k * 12288 + j];
                wt[i] = gt_w2[(size_t)k * 12288 + j];
                bg[i] = gs_b1[k];
            }
            float tp = 0.0f;
#pragma unroll
            for (int i = 0; i < 8; ++i) {
                int k = lane + 32 * i;
                tp += fmaxf(g_tph[k] + gt_b1[k], 0.0f) * wt[i];
            }
#pragma unroll
            for (int o = 16; o; o >>= 1) tp += __shfl_xor_sync(0xffffffffu, tp, o);
            float tpv = fmaxf(tp + gt_b2[j], 0.0f);
            float bsp = gs_b2[j];
#pragma unroll
            for (int tau = 0; tau < 12; ++tau) {
                float sp = 0.0f;
#pragma unroll
                for (int i = 0; i < 8; ++i)
                    sp += fmaxf(g_sph[tau * 256 + lane + 32 * i] + bg[i], 0.0f) * wg[i];
#pragma unroll
                for (int o = 16; o; o >>= 1) sp += __shfl_xor_sync(0xffffffffu, sp, o);
                if (lane == tau)
                    g_U[c * 12288 + n * 12 + tau] = fmaxf(sp + bsp, 0.0f) + tpv;
            }
        }
    } else {
        int cb = bid - 48;                  // 0..99, K chunks of 8192/100
        int k0 = (cb * 8192) / 100;
        int k1 = ((cb + 1) * 8192) / 100;
        gemv_stream<2048, false>(g_obs2, b1, fc_w1, g_s1, 0, k0, k1, 8192, sm);
    }
    grid_barrier(1);

    // ======== P2: gemv2 streamed, all 148 blocks ============================
    {
        int k0 = (bid * 2048) / 148;
        int k1 = ((bid + 1) * 2048) / 148;
        gemv_stream<2048, true>(g_s1, b1, fc_w2, g_s2, 0, k0, k1, 2048, sm);
    }
    grid_barrier(2);

    // ======== P3: gemv3 streamed (blocks 0..143) + Y (144..147) ============
    if (bid < 144) {
        int s  = bid % 6;                   // col strip
        int ci = bid / 6;                   // 0..23 k-chunk
        int k0 = (ci * 2048) / 24;
        int k1 = ((ci + 1) * 2048) / 24;
        gemv_stream<12288, true>(g_s2, b2, fc_w3, g_s3, s * 2048, k0, k1, 2048, sm);
    } else {
        int n = (bid - 144) * NTHR + tid;   // 0..2047; use first 1024
        if (n < 1024) {
            float u[12];
#pragma unroll
            for (int q = 0; q < 12; ++q) u[q] = g_U[12288 + n * 12 + q];
#pragma unroll
            for (int p = 0; p < 12; ++p) {
                float acc = 0.0f;
#pragma unroll
                for (int q = 0; q < 12; ++q) acc += Bm[p * 12 + q] * u[q];
                g_Y[n * 12 + p] = acc;
            }
        }
    }
    grid_barrier(3);

    // ======== P4: stage Y/X in smem, fused exp-adjacency + SpMM ============
    {
        float* sY   = sm;
        float* sX10 = sm + 12288;
        float* sX9  = sm + 24576;
        for (int i = tid; i < 12288 / 4; i += NTHR) {
            ((float4*)sY)[i] = ((const float4*)g_Y)[i];
            float4 bb = ((const float4*)b3)[i % 3072];
            ((float4*)sX10)[i] = relu4b(((const float4*)(g_s3 + 12288))[i], bb);
            ((float4*)sX9)[i]  = relu4b(((const float4*)g_s3)[i], bb);
        }
        __syncthreads();
        for (int task = gw; task < 3072; task += NWARP) {
            int ap = task >> 10;
            int i = task & 1023;
            int cidx = (ap == 0) ? 1 : (ap == 1 ? 0 : 2);   // a = 10,9,11
            const float* sX = (ap == 0) ? sX10 : sX9;
            float u[12];
#pragma unroll
            for (int q = 0; q < 12; ++q) u[q] = g_U[cidx * 12288 + i * 12 + q];
            float g[12];
#pragma unroll
            for (int q = 0; q < 12; ++q) g[q] = 0.0f;
            float rs = 0.0f;
            for (int j = lane; j < 1024; j += 32) {
                const float4* yr = (const float4*)(sY + j * 12);
                float4 ya = yr[0], yb = yr[1], yc = yr[2];
                float s = u[0]*ya.x + u[1]*ya.y + u[2] *ya.z + u[3] *ya.w
                        + u[4]*yb.x + u[5]*yb.y + u[6] *yb.z + u[7] *yb.w
                        + u[8]*yc.x + u[9]*yc.y + u[10]*yc.z + u[11]*yc.w;
                s = (s >= 0.05f) ? s : 0.0f;
                float e = __expf(s);
                rs += e;
                const float4* xr = (const float4*)(sX + j * 12);
                float4 xa = xr[0], xb = xr[1], xc = xr[2];
                g[0] += e*xa.x; g[1] += e*xa.y; g[2] += e*xa.z; g[3] += e*xa.w;
                g[4] += e*xb.x; g[5] += e*xb.y; g[6] += e*xb.z; g[7] += e*xb.w;
                g[8] += e*xc.x; g[9] += e*xc.y; g[10]+= e*xc.z; g[11]+= e*xc.w;
            }
#pragma unroll
            for (int o = 16; o; o >>= 1) {
                rs += __shfl_xor_sync(0xffffffffu, rs, o);
#pragma unroll
                for (int q = 0; q < 12; ++q)
                    g[q] += __shfl_xor_sync(0xffffffffu, g[q], o);
            }
            if (lane == 0) {
                float inv = 1.0f / rs;
                float* G = g_G + task * 12;
#pragma unroll
                for (int q = 0; q < 12; ++q) G[q] = g[q] * inv;
            }
        }
    }
    grid_barrier(4);

    // ======== P5: combine + zero accumulators ==============================
    if (gt < 12288 + 35840) {
        int idx = gt;
        if (idx < 12288) {
            int n = idx / 12, f = idx % 12;
            float acc1 = bvec[f], acc2 = bvec[f];
#pragma unroll
            for (int q = 0; q < 12; ++q) {
                acc1 += g_G[n * 12 + q] * (Wf[q * 12 + f] + Wb[q * 12 + f]);
                acc2 += g_G[(1024 + n) * 12 + q] * Wf[144 + q * 12 + f]
                      + g_G[(2048 + n) * 12 + q] * Wb[144 + q * 12 + f];
            }
            out[idx] = fmaxf(acc1, 0.0f) + fmaxf(acc2, 0.0f);
        } else {
            int i = idx - 12288;
            if (i < 4096)        g_s1[i] = 0.0f;
            else if (i < 8192)   g_s2[i - 4096] = 0.0f;
            else if (i < 32768)  g_s3[i - 8192] = 0.0f;
            else                 g_sph[i - 32768] = 0.0f;
        }
    }
}

// ---------------- launch ----------------
extern "C" void kernel_launch(void* const* d_in, const int* in_sizes, int n_in,
                              void* d_out, int out_size) {
    const float* obs    = (const float*)d_in[0];
    const float* tf     = (const float*)d_in[1];
    const float* fc_w1  = (const float*)d_in[2];
    const float* fc_b1  = (const float*)d_in[3];
    const float* fc_w2  = (const float*)d_in[4];
    const float* fc_b2  = (const float*)d_in[5];
    const float* fc_w3  = (const float*)d_in[6];
    const float* fc_b3  = (const float*)d_in[7];
    const float* Wf     = (const float*)d_in[8];
    const float* Wb     = (const float*)d_in[9];
    const float* bvec   = (const float*)d_in[10];
    const float* li     = (const float*)d_in[11];
    const float* gs_w1  = (const float*)d_in[12];
    const float* gs_b1  = (const float*)d_in[13];
    const float* gs_w2  = (const float*)d_in[14];
    const float* gs_b2  = (const float*)d_in[15];
    const float* gt_w1  = (const float*)d_in[16];
    const float* gt_b1  = (const float*)d_in[17];
    const float* gt_w2  = (const float*)d_in[18];
    const float* gt_b2  = (const float*)d_in[19];
    const float* Bm     = (const float*)d_in[20];
    float* out = (float*)d_out;

    cudaFuncSetAttribute(mega8_kernel,
                         cudaFuncAttributeMaxDynamicSharedMemorySize,
                         SMEM_FLOATS * sizeof(float));

    mega8_kernel<<<NBLK, NTHR, SMEM_FLOATS * sizeof(float)>>>(
        obs, tf, fc_w1, fc_b1, fc_w2, fc_b2, fc_w3, fc_b3,
        Wf, Wb, bvec, li, gs_w1, gs_b1, gs_w2, gs_b2,
        gt_w1, gt_b1, gt_w2, gt_b2, Bm, out);
}